// round 6
// baseline (speedup 1.0000x reference)
#include <cuda_runtime.h>

// Problem constants
#define Bc 4
#define Lc 512
#define Dc 768
#define Wc 12
#define Mrows   (Bc * Lc)          // 2048
#define Mout    (Bc * Lc * Wc)     // 24576
#define Kproj   Dc                 // 768
#define Nproj   (2 * Dc)           // 1536
#define Kout    (3 * Dc)           // 2304
#define Nout    Dc                 // 768

// GEMM tiling
#define BM 128
#define BN 128
#define BKK 8
#define TM 8
#define TN 8
#define NTHREADS 256

// Scratch (device globals; allocation is forbidden)
__device__ float g_proj[Mrows * Nproj];          // 12.6 MB  [b*L+l][e]
__device__ float g_conv[(size_t)Mout * Dc];      // 75.5 MB  [((b*L+l)*W+k)][o]
__device__ float g_cw[Wc * Dc * Dc];             // 28.3 MB  [k][o][c]

// ---------------------------------------------------------------------------
// Pack conv_w (o, c, k) -> (k, o, c) for coalesced GEMM-B loads
// ---------------------------------------------------------------------------
__global__ void pack_convw(const float* __restrict__ cw) {
    int i = blockIdx.x * blockDim.x + threadIdx.x;
    if (i >= Wc * Dc * Dc) return;
    int c = i % Dc;
    int t = i / Dc;
    int o = t % Dc;
    int k = t / Dc;
    g_cw[i] = cw[(o * Dc + c) * Wc + k];
}

// ---------------------------------------------------------------------------
// GEMM 1: proj[m, e] = sum_d h[m, d] * proj_w[e, d] + proj_b[e]
//   M=2048, N=1536, K=768
// ---------------------------------------------------------------------------
__global__ __launch_bounds__(NTHREADS)
void gemm_proj(const float* __restrict__ A, const float* __restrict__ Bw,
               const float* __restrict__ bias) {
    __shared__ float As[BKK][BM];
    __shared__ float Bs[BKK][BN];
    const int K = Kproj, N = Nproj;
    int bm = blockIdx.y * BM, bn = blockIdx.x * BN;
    int t = threadIdx.x;
    int lr = t >> 1, lc4 = (t & 1) * 4;
    int ty = t >> 4, tx = t & 15;

    float acc[TM][TN];
#pragma unroll
    for (int i = 0; i < TM; i++)
#pragma unroll
        for (int j = 0; j < TN; j++) acc[i][j] = 0.f;

    for (int k0 = 0; k0 < K; k0 += BKK) {
        float4 av = *(const float4*)(A + (size_t)(bm + lr) * K + k0 + lc4);
        As[lc4 + 0][lr] = av.x; As[lc4 + 1][lr] = av.y;
        As[lc4 + 2][lr] = av.z; As[lc4 + 3][lr] = av.w;
        float4 bv = *(const float4*)(Bw + (size_t)(bn + lr) * K + k0 + lc4);
        Bs[lc4 + 0][lr] = bv.x; Bs[lc4 + 1][lr] = bv.y;
        Bs[lc4 + 2][lr] = bv.z; Bs[lc4 + 3][lr] = bv.w;
        __syncthreads();
#pragma unroll
        for (int kk = 0; kk < BKK; kk++) {
            float ar[TM], br[TN];
#pragma unroll
            for (int i = 0; i < TM; i++) ar[i] = As[kk][ty * TM + i];
#pragma unroll
            for (int j = 0; j < TN; j++) br[j] = Bs[kk][tx * TN + j];
#pragma unroll
            for (int i = 0; i < TM; i++)
#pragma unroll
                for (int j = 0; j < TN; j++) acc[i][j] += ar[i] * br[j];
        }
        __syncthreads();
    }

    float bvv[TN];
#pragma unroll
    for (int j = 0; j < TN; j++) bvv[j] = bias[bn + tx * TN + j];
#pragma unroll
    for (int i = 0; i < TM; i++) {
        int gm = bm + ty * TM + i;
        float4 v0, v1;
        v0.x = acc[i][0] + bvv[0]; v0.y = acc[i][1] + bvv[1];
        v0.z = acc[i][2] + bvv[2]; v0.w = acc[i][3] + bvv[3];
        v1.x = acc[i][4] + bvv[4]; v1.y = acc[i][5] + bvv[5];
        v1.z = acc[i][6] + bvv[6]; v1.w = acc[i][7] + bvv[7];
        *(float4*)(g_proj + (size_t)gm * N + bn + tx * TN)     = v0;
        *(float4*)(g_proj + (size_t)gm * N + bn + tx * TN + 4) = v1;
    }
}

// ---------------------------------------------------------------------------
// GEMM 2: P[m, o; k] = sum_c h[b, l+k, c] * g_cw[k][o][c]   (0 if l+k >= L)
//   grid.z = k. M=2048, N=768, K=768. Output indexed [m*W + k][o].
// ---------------------------------------------------------------------------
__global__ __launch_bounds__(NTHREADS)
void gemm_conv(const float* __restrict__ h) {
    __shared__ float As[BKK][BM];
    __shared__ float Bs[BKK][BN];
    const int K = Dc, N = Dc;
    int kz = blockIdx.z;
    int bm = blockIdx.y * BM, bn = blockIdx.x * BN;
    int t = threadIdx.x;
    int lr = t >> 1, lc4 = (t & 1) * 4;
    int ty = t >> 4, tx = t & 15;

    // per-thread A row (constant over k-loop)
    int m = bm + lr;
    int b = m >> 9;           // /512
    int l = m & 511;
    int ls = l + kz;
    const float* arow = (ls < Lc) ? (h + ((size_t)(b * Lc + ls)) * Dc) : nullptr;
    const float* brow = g_cw + (size_t)kz * Dc * Dc + (size_t)(bn + lr) * K;

    float acc[TM][TN];
#pragma unroll
    for (int i = 0; i < TM; i++)
#pragma unroll
        for (int j = 0; j < TN; j++) acc[i][j] = 0.f;

    for (int k0 = 0; k0 < K; k0 += BKK) {
        float4 av = make_float4(0.f, 0.f, 0.f, 0.f);
        if (arow) av = *(const float4*)(arow + k0 + lc4);
        As[lc4 + 0][lr] = av.x; As[lc4 + 1][lr] = av.y;
        As[lc4 + 2][lr] = av.z; As[lc4 + 3][lr] = av.w;
        float4 bv = *(const float4*)(brow + k0 + lc4);
        Bs[lc4 + 0][lr] = bv.x; Bs[lc4 + 1][lr] = bv.y;
        Bs[lc4 + 2][lr] = bv.z; Bs[lc4 + 3][lr] = bv.w;
        __syncthreads();
#pragma unroll
        for (int kk = 0; kk < BKK; kk++) {
            float ar[TM], br[TN];
#pragma unroll
            for (int i = 0; i < TM; i++) ar[i] = As[kk][ty * TM + i];
#pragma unroll
            for (int j = 0; j < TN; j++) br[j] = Bs[kk][tx * TN + j];
#pragma unroll
            for (int i = 0; i < TM; i++)
#pragma unroll
                for (int j = 0; j < TN; j++) acc[i][j] += ar[i] * br[j];
        }
        __syncthreads();
    }

#pragma unroll
    for (int i = 0; i < TM; i++) {
        int gm = bm + ty * TM + i;
        size_t base = ((size_t)gm * Wc + kz) * (size_t)N + bn + tx * TN;
        float4 v0, v1;
        v0.x = acc[i][0]; v0.y = acc[i][1]; v0.z = acc[i][2]; v0.w = acc[i][3];
        v1.x = acc[i][4]; v1.y = acc[i][5]; v1.z = acc[i][6]; v1.w = acc[i][7];
        *(float4*)(g_conv + base)     = v0;
        *(float4*)(g_conv + base + 4) = v1;
    }
}

// ---------------------------------------------------------------------------
// Cumsum over k (W=12) in-place on g_conv
// ---------------------------------------------------------------------------
__global__ void cumsum_k() {
    int i = blockIdx.x * blockDim.x + threadIdx.x;   // over 2048*768
    if (i >= Mrows * Dc) return;
    int o = i % Dc;
    int m = i / Dc;
    float* p = g_conv + (size_t)m * Wc * Dc + o;
    float s = 0.f;
#pragma unroll
    for (int k = 0; k < Wc; k++) {
        s += p[(size_t)k * Dc];
        p[(size_t)k * Dc] = s;
    }
}

// ---------------------------------------------------------------------------
// GEMM 3 (gathered): out[m, d] = relu( sum_f relu(cat[m,f]) * out_w[d,f] + ob[d] )
//   M=24576, N=768, K=2304
//   cat[m, f]: f<768  -> g_proj[(b*512+sidx)*1536 + f]
//              f<1536 -> g_proj[(b*512+eidx)*1536 + 768 + (f-768)]
//              else   -> g_conv[m*768 + (f-1536)]
//   NOTE: span_idx arrives as int32 (JAX silently downgrades int64 without
//   x64 mode) — read as int pairs.
// ---------------------------------------------------------------------------
__global__ __launch_bounds__(NTHREADS)
void gemm_out(const int* __restrict__ span,
              const float* __restrict__ Wout,
              const float* __restrict__ bias,
              float* __restrict__ out) {
    __shared__ float As[BKK][BM];
    __shared__ float Bs[BKK][BN];
    const int K = Kout, N = Nout;
    int bm = blockIdx.y * BM, bn = blockIdx.x * BN;
    int t = threadIdx.x;
    int lr = t >> 1, lc4 = (t & 1) * 4;
    int ty = t >> 4, tx = t & 15;

    // per-thread gathered A row bases (constant over k-loop)
    int m = bm + lr;
    int b = m / (Lc * Wc);
    int si = span[(size_t)m * 2 + 0];
    int ei = span[(size_t)m * 2 + 1];
    si = si < 0 ? 0 : (si > Lc - 1 ? Lc - 1 : si);
    ei = ei < 0 ? 0 : (ei > Lc - 1 ? Lc - 1 : ei);
    const float* p0 = g_proj + (size_t)(b * Lc + si) * Nproj;
    const float* p1 = g_proj + (size_t)(b * Lc + ei) * Nproj + Dc;
    const float* p2 = g_conv + (size_t)m * Dc;
    const float* brow = Wout + (size_t)(bn + lr) * K;

    float acc[TM][TN];
#pragma unroll
    for (int i = 0; i < TM; i++)
#pragma unroll
        for (int j = 0; j < TN; j++) acc[i][j] = 0.f;

    for (int k0 = 0; k0 < K; k0 += BKK) {
        int f = k0 + lc4;
        const float* src;
        if (f < Dc)            src = p0 + f;
        else if (f < 2 * Dc)   src = p1 + (f - Dc);
        else                   src = p2 + (f - 2 * Dc);
        float4 av = *(const float4*)src;
        As[lc4 + 0][lr] = fmaxf(av.x, 0.f);
        As[lc4 + 1][lr] = fmaxf(av.y, 0.f);
        As[lc4 + 2][lr] = fmaxf(av.z, 0.f);
        As[lc4 + 3][lr] = fmaxf(av.w, 0.f);
        float4 bv = *(const float4*)(brow + k0 + lc4);
        Bs[lc4 + 0][lr] = bv.x; Bs[lc4 + 1][lr] = bv.y;
        Bs[lc4 + 2][lr] = bv.z; Bs[lc4 + 3][lr] = bv.w;
        __syncthreads();
#pragma unroll
        for (int kk = 0; kk < BKK; kk++) {
            float ar[TM], br[TN];
#pragma unroll
            for (int i = 0; i < TM; i++) ar[i] = As[kk][ty * TM + i];
#pragma unroll
            for (int j = 0; j < TN; j++) br[j] = Bs[kk][tx * TN + j];
#pragma unroll
            for (int i = 0; i < TM; i++)
#pragma unroll
                for (int j = 0; j < TN; j++) acc[i][j] += ar[i] * br[j];
        }
        __syncthreads();
    }

    float bvv[TN];
#pragma unroll
    for (int j = 0; j < TN; j++) bvv[j] = bias[bn + tx * TN + j];
#pragma unroll
    for (int i = 0; i < TM; i++) {
        int gm = bm + ty * TM + i;
        float4 v0, v1;
        v0.x = fmaxf(acc[i][0] + bvv[0], 0.f);
        v0.y = fmaxf(acc[i][1] + bvv[1], 0.f);
        v0.z = fmaxf(acc[i][2] + bvv[2], 0.f);
        v0.w = fmaxf(acc[i][3] + bvv[3], 0.f);
        v1.x = fmaxf(acc[i][4] + bvv[4], 0.f);
        v1.y = fmaxf(acc[i][5] + bvv[5], 0.f);
        v1.z = fmaxf(acc[i][6] + bvv[6], 0.f);
        v1.w = fmaxf(acc[i][7] + bvv[7], 0.f);
        *(float4*)(out + (size_t)gm * N + bn + tx * TN)     = v0;
        *(float4*)(out + (size_t)gm * N + bn + tx * TN + 4) = v1;
    }
}

// ---------------------------------------------------------------------------
extern "C" void kernel_launch(void* const* d_in, const int* in_sizes, int n_in,
                              void* d_out, int out_size) {
    const float* h    = (const float*)d_in[0];
    const int*   span = (const int*)d_in[1];
    const float* pw   = (const float*)d_in[2];
    const float* pb   = (const float*)d_in[3];
    const float* cw   = (const float*)d_in[4];
    const float* ow   = (const float*)d_in[5];
    const float* ob   = (const float*)d_in[6];
    float* out = (float*)d_out;
    (void)in_sizes; (void)n_in; (void)out_size;

    pack_convw<<<(Wc * Dc * Dc + 255) / 256, 256>>>(cw);
    gemm_proj<<<dim3(Nproj / BN, Mrows / BM), NTHREADS>>>(h, pw, pb);
    gemm_conv<<<dim3(Dc / BN, Mrows / BM, Wc), NTHREADS>>>(h);
    cumsum_k<<<(Mrows * Dc + 255) / 256, 256>>>();
    gemm_out<<<dim3(Nout / BN, Mout / BM), NTHREADS>>>(span, ow, ob, out);
}

// round 9
// speedup vs baseline: 1.0003x; 1.0003x over previous
#include <cuda_runtime.h>

// Problem constants
#define Bc 4
#define Lc 512
#define Dc 768
#define Wc 12
#define Mrows   (Bc * Lc)          // 2048
#define Mout    (Bc * Lc * Wc)     // 24576
#define Kproj   Dc                 // 768
#define Nproj   (2 * Dc)           // 1536
#define Kout    (3 * Dc)           // 2304
#define Nout    Dc                 // 768

// GEMM tiling
#define BM 128
#define BN 128
#define BKK 8
#define TM 8
#define TN 8
#define NTHREADS 256

// Scratch (device globals; allocation is forbidden)
__device__ float g_proj[Mrows * Nproj];          // 12.6 MB  [b*L+l][e]
__device__ float g_conv[(size_t)Mout * Dc];      // 75.5 MB  [((b*L+l)*W+k)][o]
__device__ float g_cw[Wc * Dc * Dc];             // 28.3 MB  [k][o][c]

// ---------------------------------------------------------------------------
// Pack conv_w (o, c, k) -> (k, o, c) for coalesced GEMM-B loads
// ---------------------------------------------------------------------------
__global__ void pack_convw(const float* __restrict__ cw) {
    int i = blockIdx.x * blockDim.x + threadIdx.x;
    if (i >= Wc * Dc * Dc) return;
    int c = i % Dc;
    int t = i / Dc;
    int o = t % Dc;
    int k = t / Dc;
    g_cw[i] = cw[(o * Dc + c) * Wc + k];
}

// ---------------------------------------------------------------------------
// GEMM 1: proj[m, e] = sum_d h[m, d] * proj_w[e, d] + proj_b[e]
//   M=2048, N=1536, K=768
// ---------------------------------------------------------------------------
__global__ __launch_bounds__(NTHREADS)
void gemm_proj(const float* __restrict__ A, const float* __restrict__ Bw,
               const float* __restrict__ bias) {
    __shared__ float As[BKK][BM];
    __shared__ float Bs[BKK][BN];
    const int K = Kproj, N = Nproj;
    int bm = blockIdx.y * BM, bn = blockIdx.x * BN;
    int t = threadIdx.x;
    int lr = t >> 1, lc4 = (t & 1) * 4;
    int ty = t >> 4, tx = t & 15;

    float acc[TM][TN];
#pragma unroll
    for (int i = 0; i < TM; i++)
#pragma unroll
        for (int j = 0; j < TN; j++) acc[i][j] = 0.f;

    for (int k0 = 0; k0 < K; k0 += BKK) {
        float4 av = *(const float4*)(A + (size_t)(bm + lr) * K + k0 + lc4);
        As[lc4 + 0][lr] = av.x; As[lc4 + 1][lr] = av.y;
        As[lc4 + 2][lr] = av.z; As[lc4 + 3][lr] = av.w;
        float4 bv = *(const float4*)(Bw + (size_t)(bn + lr) * K + k0 + lc4);
        Bs[lc4 + 0][lr] = bv.x; Bs[lc4 + 1][lr] = bv.y;
        Bs[lc4 + 2][lr] = bv.z; Bs[lc4 + 3][lr] = bv.w;
        __syncthreads();
#pragma unroll
        for (int kk = 0; kk < BKK; kk++) {
            float ar[TM], br[TN];
#pragma unroll
            for (int i = 0; i < TM; i++) ar[i] = As[kk][ty * TM + i];
#pragma unroll
            for (int j = 0; j < TN; j++) br[j] = Bs[kk][tx * TN + j];
#pragma unroll
            for (int i = 0; i < TM; i++)
#pragma unroll
                for (int j = 0; j < TN; j++) acc[i][j] += ar[i] * br[j];
        }
        __syncthreads();
    }

    float bvv[TN];
#pragma unroll
    for (int j = 0; j < TN; j++) bvv[j] = bias[bn + tx * TN + j];
#pragma unroll
    for (int i = 0; i < TM; i++) {
        int gm = bm + ty * TM + i;
        float4 v0, v1;
        v0.x = acc[i][0] + bvv[0]; v0.y = acc[i][1] + bvv[1];
        v0.z = acc[i][2] + bvv[2]; v0.w = acc[i][3] + bvv[3];
        v1.x = acc[i][4] + bvv[4]; v1.y = acc[i][5] + bvv[5];
        v1.z = acc[i][6] + bvv[6]; v1.w = acc[i][7] + bvv[7];
        *(float4*)(g_proj + (size_t)gm * N + bn + tx * TN)     = v0;
        *(float4*)(g_proj + (size_t)gm * N + bn + tx * TN + 4) = v1;
    }
}

// ---------------------------------------------------------------------------
// GEMM 2: P[m, o; k] = sum_c h[b, l+k, c] * g_cw[k][o][c]   (0 if l+k >= L)
//   grid.z = k. M=2048, N=768, K=768. Output indexed [m*W + k][o].
// ---------------------------------------------------------------------------
__global__ __launch_bounds__(NTHREADS)
void gemm_conv(const float* __restrict__ h) {
    __shared__ float As[BKK][BM];
    __shared__ float Bs[BKK][BN];
    const int K = Dc, N = Dc;
    int kz = blockIdx.z;
    int bm = blockIdx.y * BM, bn = blockIdx.x * BN;
    int t = threadIdx.x;
    int lr = t >> 1, lc4 = (t & 1) * 4;
    int ty = t >> 4, tx = t & 15;

    // per-thread A row (constant over k-loop)
    int m = bm + lr;
    int b = m >> 9;           // /512
    int l = m & 511;
    int ls = l + kz;
    const float* arow = (ls < Lc) ? (h + ((size_t)(b * Lc + ls)) * Dc) : nullptr;
    const float* brow = g_cw + (size_t)kz * Dc * Dc + (size_t)(bn + lr) * K;

    float acc[TM][TN];
#pragma unroll
    for (int i = 0; i < TM; i++)
#pragma unroll
        for (int j = 0; j < TN; j++) acc[i][j] = 0.f;

    for (int k0 = 0; k0 < K; k0 += BKK) {
        float4 av = make_float4(0.f, 0.f, 0.f, 0.f);
        if (arow) av = *(const float4*)(arow + k0 + lc4);
        As[lc4 + 0][lr] = av.x; As[lc4 + 1][lr] = av.y;
        As[lc4 + 2][lr] = av.z; As[lc4 + 3][lr] = av.w;
        float4 bv = *(const float4*)(brow + k0 + lc4);
        Bs[lc4 + 0][lr] = bv.x; Bs[lc4 + 1][lr] = bv.y;
        Bs[lc4 + 2][lr] = bv.z; Bs[lc4 + 3][lr] = bv.w;
        __syncthreads();
#pragma unroll
        for (int kk = 0; kk < BKK; kk++) {
            float ar[TM], br[TN];
#pragma unroll
            for (int i = 0; i < TM; i++) ar[i] = As[kk][ty * TM + i];
#pragma unroll
            for (int j = 0; j < TN; j++) br[j] = Bs[kk][tx * TN + j];
#pragma unroll
            for (int i = 0; i < TM; i++)
#pragma unroll
                for (int j = 0; j < TN; j++) acc[i][j] += ar[i] * br[j];
        }
        __syncthreads();
    }

#pragma unroll
    for (int i = 0; i < TM; i++) {
        int gm = bm + ty * TM + i;
        size_t base = ((size_t)gm * Wc + kz) * (size_t)N + bn + tx * TN;
        float4 v0, v1;
        v0.x = acc[i][0]; v0.y = acc[i][1]; v0.z = acc[i][2]; v0.w = acc[i][3];
        v1.x = acc[i][4]; v1.y = acc[i][5]; v1.z = acc[i][6]; v1.w = acc[i][7];
        *(float4*)(g_conv + base)     = v0;
        *(float4*)(g_conv + base + 4) = v1;
    }
}

// ---------------------------------------------------------------------------
// Cumsum over k (W=12) in-place on g_conv
// ---------------------------------------------------------------------------
__global__ void cumsum_k() {
    int i = blockIdx.x * blockDim.x + threadIdx.x;   // over 2048*768
    if (i >= Mrows * Dc) return;
    int o = i % Dc;
    int m = i / Dc;
    float* p = g_conv + (size_t)m * Wc * Dc + o;
    float s = 0.f;
#pragma unroll
    for (int k = 0; k < Wc; k++) {
        s += p[(size_t)k * Dc];
        p[(size_t)k * Dc] = s;
    }
}

// ---------------------------------------------------------------------------
// GEMM 3 (gathered): out[m, d] = relu( sum_f relu(cat[m,f]) * out_w[d,f] + ob[d] )
//   M=24576, N=768, K=2304
//   cat[m, f]: f<768  -> g_proj[(b*512+sidx)*1536 + f]
//              f<1536 -> g_proj[(b*512+eidx)*1536 + 768 + (f-768)]
//              else   -> g_conv[m*768 + (f-1536)]
//   NOTE: span_idx arrives as int32 (JAX silently downgrades int64 without
//   x64 mode) — read as int pairs.
// ---------------------------------------------------------------------------
__global__ __launch_bounds__(NTHREADS)
void gemm_out(const int* __restrict__ span,
              const float* __restrict__ Wout,
              const float* __restrict__ bias,
              float* __restrict__ out) {
    __shared__ float As[BKK][BM];
    __shared__ float Bs[BKK][BN];
    const int K = Kout, N = Nout;
    int bm = blockIdx.y * BM, bn = blockIdx.x * BN;
    int t = threadIdx.x;
    int lr = t >> 1, lc4 = (t & 1) * 4;
    int ty = t >> 4, tx = t & 15;

    // per-thread gathered A row bases (constant over k-loop)
    int m = bm + lr;
    int b = m / (Lc * Wc);
    int si = span[(size_t)m * 2 + 0];
    int ei = span[(size_t)m * 2 + 1];
    si = si < 0 ? 0 : (si > Lc - 1 ? Lc - 1 : si);
    ei = ei < 0 ? 0 : (ei > Lc - 1 ? Lc - 1 : ei);
    const float* p0 = g_proj + (size_t)(b * Lc + si) * Nproj;
    const float* p1 = g_proj + (size_t)(b * Lc + ei) * Nproj + Dc;
    const float* p2 = g_conv + (size_t)m * Dc;
    const float* brow = Wout + (size_t)(bn + lr) * K;

    float acc[TM][TN];
#pragma unroll
    for (int i = 0; i < TM; i++)
#pragma unroll
        for (int j = 0; j < TN; j++) acc[i][j] = 0.f;

    for (int k0 = 0; k0 < K; k0 += BKK) {
        int f = k0 + lc4;
        const float* src;
        if (f < Dc)            src = p0 + f;
        else if (f < 2 * Dc)   src = p1 + (f - Dc);
        else                   src = p2 + (f - 2 * Dc);
        float4 av = *(const float4*)src;
        As[lc4 + 0][lr] = fmaxf(av.x, 0.f);
        As[lc4 + 1][lr] = fmaxf(av.y, 0.f);
        As[lc4 + 2][lr] = fmaxf(av.z, 0.f);
        As[lc4 + 3][lr] = fmaxf(av.w, 0.f);
        float4 bv = *(const float4*)(brow + k0 + lc4);
        Bs[lc4 + 0][lr] = bv.x; Bs[lc4 + 1][lr] = bv.y;
        Bs[lc4 + 2][lr] = bv.z; Bs[lc4 + 3][lr] = bv.w;
        __syncthreads();
#pragma unroll
        for (int kk = 0; kk < BKK; kk++) {
            float ar[TM], br[TN];
#pragma unroll
            for (int i = 0; i < TM; i++) ar[i] = As[kk][ty * TM + i];
#pragma unroll
            for (int j = 0; j < TN; j++) br[j] = Bs[kk][tx * TN + j];
#pragma unroll
            for (int i = 0; i < TM; i++)
#pragma unroll
                for (int j = 0; j < TN; j++) acc[i][j] += ar[i] * br[j];
        }
        __syncthreads();
    }

    float bvv[TN];
#pragma unroll
    for (int j = 0; j < TN; j++) bvv[j] = bias[bn + tx * TN + j];
#pragma unroll
    for (int i = 0; i < TM; i++) {
        int gm = bm + ty * TM + i;
        float4 v0, v1;
        v0.x = fmaxf(acc[i][0] + bvv[0], 0.f);
        v0.y = fmaxf(acc[i][1] + bvv[1], 0.f);
        v0.z = fmaxf(acc[i][2] + bvv[2], 0.f);
        v0.w = fmaxf(acc[i][3] + bvv[3], 0.f);
        v1.x = fmaxf(acc[i][4] + bvv[4], 0.f);
        v1.y = fmaxf(acc[i][5] + bvv[5], 0.f);
        v1.z = fmaxf(acc[i][6] + bvv[6], 0.f);
        v1.w = fmaxf(acc[i][7] + bvv[7], 0.f);
        *(float4*)(out + (size_t)gm * N + bn + tx * TN)     = v0;
        *(float4*)(out + (size_t)gm * N + bn + tx * TN + 4) = v1;
    }
}

// ---------------------------------------------------------------------------
extern "C" void kernel_launch(void* const* d_in, const int* in_sizes, int n_in,
                              void* d_out, int out_size) {
    const float* h    = (const float*)d_in[0];
    const int*   span = (const int*)d_in[1];
    const float* pw   = (const float*)d_in[2];
    const float* pb   = (const float*)d_in[3];
    const float* cw   = (const float*)d_in[4];
    const float* ow   = (const float*)d_in[5];
    const float* ob   = (const float*)d_in[6];
    float* out = (float*)d_out;
    (void)in_sizes; (void)n_in; (void)out_size;

    pack_convw<<<(Wc * Dc * Dc + 255) / 256, 256>>>(cw);
    gemm_proj<<<dim3(Nproj / BN, Mrows / BM), NTHREADS>>>(h, pw, pb);
    gemm_conv<<<dim3(Dc / BN, Mrows / BM, Wc), NTHREADS>>>(h);
    cumsum_k<<<(Mrows * Dc + 255) / 256, 256>>>();
    gemm_out<<<dim3(Nout / BN, Mout / BM), NTHREADS>>>(span, ow, ob, out);
}